// round 1
// baseline (speedup 1.0000x reference)
#include <cuda_runtime.h>
#include <cstdint>

#define BLOCK 128
typedef unsigned long long ull;

// ---- packed f32x2 helpers (sm_103a) ----
__device__ __forceinline__ ull fma2(ull a, ull b, ull c) {
    ull d;
    asm("fma.rn.f32x2 %0, %1, %2, %3;" : "=l"(d) : "l"(a), "l"(b), "l"(c));
    return d;
}
__device__ __forceinline__ ull add2(ull a, ull b) {
    ull d;
    asm("add.rn.f32x2 %0, %1, %2;" : "=l"(d) : "l"(a), "l"(b));
    return d;
}
__device__ __forceinline__ ull pack2(float lo, float hi) {
    ull r;
    asm("mov.b64 %0, {%1, %2};" : "=l"(r) : "f"(lo), "f"(hi));
    return r;
}
__device__ __forceinline__ void unpack2(ull v, float& lo, float& hi) {
    asm("mov.b64 {%0, %1}, %2;" : "=f"(lo), "=f"(hi) : "l"(v));
}
__device__ __forceinline__ ull dup2(float v) {
    unsigned u = __float_as_uint(v);
    return ((ull)u << 32) | (ull)u;
}

// quantize step: trunc((xx + sign(xx)*128)/256) == trunc(xx/256 + copysign(0.5,xx))
// (both forms exact in fp32 for |xx| < 2^30; sign(0) edge agrees: trunc(+-0.5)=+-0)
__device__ __forceinline__ float armq(float xx) {
    float t = fmaf(xx, 0.00390625f, copysignf(0.5f, xx));
    return truncf(t);
}

#define C256X2 0x4380000043800000ULL  // (256.f, 256.f)

__global__ void __launch_bounds__(BLOCK) armint_kernel(
    const float* __restrict__ x,
    const float* __restrict__ w0, const float* __restrict__ b0,
    const float* __restrict__ w1, const float* __restrict__ b1,
    const float* __restrict__ w_out, const float* __restrict__ b_out,
    float* __restrict__ out, int B)
{
    // weights duplicated into both f32x2 halves, once per block
    __shared__ __align__(16) ull sw0[1024];
    __shared__ __align__(16) ull sw1[1024];
    __shared__ __align__(16) ull swo[64];
    __shared__ ull sb0[32], sb1[32], sbo[2];

    for (int i = threadIdx.x; i < 1024; i += BLOCK) {
        sw0[i] = dup2(w0[i]);
        sw1[i] = dup2(w1[i]);
    }
    if (threadIdx.x < 64) swo[threadIdx.x] = dup2(w_out[threadIdx.x]);
    if (threadIdx.x < 32) {
        sb0[threadIdx.x] = dup2(b0[threadIdx.x]);
        sb1[threadIdx.x] = dup2(b1[threadIdx.x]);
    }
    if (threadIdx.x < 2) sbo[threadIdx.x] = dup2(b_out[threadIdx.x]);
    __syncthreads();

    const int warp = threadIdx.x >> 5;
    const int lane = threadIdx.x & 31;
    const long long ubase = ((long long)blockIdx.x * (BLOCK / 32) + warp) * 64;
    const long long rowA = ubase + lane;
    const long long rowB = ubase + 32 + lane;
    const bool vA = rowA < (long long)B;
    const bool vB = rowB < (long long)B;

    // h = x * 256, two rows packed per f32x2 register
    ull h[32];
    {
        const float4* pa = (const float4*)(x + rowA * 32);
        const float4* pb = (const float4*)(x + rowB * 32);
        #pragma unroll
        for (int i = 0; i < 8; i++) {
            float4 a = vA ? __ldcs(pa + i) : make_float4(0.f, 0.f, 0.f, 0.f);
            float4 b = vB ? __ldcs(pb + i) : make_float4(0.f, 0.f, 0.f, 0.f);
            h[4 * i + 0] = pack2(a.x * 256.f, b.x * 256.f);
            h[4 * i + 1] = pack2(a.y * 256.f, b.y * 256.f);
            h[4 * i + 2] = pack2(a.z * 256.f, b.z * 256.f);
            h[4 * i + 3] = pack2(a.w * 256.f, b.w * 256.f);
        }
    }

    // two hidden layers: xx = h@W^T + b + 256*h ; h' = relu(trunc((xx+sign*128)/256))
    #define ARM_LAYER(SW, SB)                                                    \
    do {                                                                         \
        ull nh[32];                                                              \
        _Pragma("unroll")                                                        \
        for (int j = 0; j < 32; j++) {                                           \
            const ulonglong2* wr = (const ulonglong2*)((SW) + j * 32);           \
            ull acc0 = fma2(h[j], C256X2, (SB)[j]);  /* residual + bias */       \
            ull acc1 = 0ULL;                                                     \
            _Pragma("unroll")                                                    \
            for (int kk = 0; kk < 16; kk++) {                                    \
                ulonglong2 w = wr[kk];                                           \
                acc0 = fma2(h[2 * kk + 0], w.x, acc0);                           \
                acc1 = fma2(h[2 * kk + 1], w.y, acc1);                           \
            }                                                                    \
            ull acc = add2(acc0, acc1);                                          \
            float lo, hi;                                                        \
            unpack2(acc, lo, hi);                                                \
            lo = fmaxf(armq(lo), 0.f);                                           \
            hi = fmaxf(armq(hi), 0.f);                                           \
            nh[j] = pack2(lo, hi);                                               \
        }                                                                        \
        _Pragma("unroll")                                                        \
        for (int j = 0; j < 32; j++) h[j] = nh[j];                               \
    } while (0)

    ARM_LAYER(sw0, sb0);
    ARM_LAYER(sw1, sb1);

    // output layer (2 neurons, no residual), then raw = hq/256
    float raw_lo[2], raw_hi[2];
    #pragma unroll
    for (int j = 0; j < 2; j++) {
        const ulonglong2* wr = (const ulonglong2*)(swo + j * 32);
        ull acc0 = sbo[j];
        ull acc1 = 0ULL;
        #pragma unroll
        for (int kk = 0; kk < 16; kk++) {
            ulonglong2 w = wr[kk];
            acc0 = fma2(h[2 * kk + 0], w.x, acc0);
            acc1 = fma2(h[2 * kk + 1], w.y, acc1);
        }
        ull acc = add2(acc0, acc1);
        float lo, hi;
        unpack2(acc, lo, hi);
        raw_lo[j] = armq(lo) * 0.00390625f;
        raw_hi[j] = armq(hi) * 0.00390625f;
    }

    const float mu_lo = raw_lo[0], ls_lo = raw_lo[1];
    const float mu_hi = raw_hi[0], ls_hi = raw_hi[1];
    const float sc_lo = __expf(0.f) == 1.f  // force no contraction weirdness; use expf below
                        ? expf(fminf(fmaxf(ls_lo - 4.0f, -4.6f), 5.0f)) : 0.f;
    const float sc_hi = expf(fminf(fmaxf(ls_hi - 4.0f, -4.6f), 5.0f));

    const size_t Bz = (size_t)B;
    if (vA) {
        out[(size_t)rowA]          = mu_lo;
        out[Bz + (size_t)rowA]     = sc_lo;
        out[2 * Bz + (size_t)rowA] = ls_lo;
    }
    if (vB) {
        out[(size_t)rowB]          = mu_hi;
        out[Bz + (size_t)rowB]     = sc_hi;
        out[2 * Bz + (size_t)rowB] = ls_hi;
    }
}

extern "C" void kernel_launch(void* const* d_in, const int* in_sizes, int n_in,
                              void* d_out, int out_size)
{
    const float* x     = (const float*)d_in[0];
    const float* w0    = (const float*)d_in[1];
    const float* b0    = (const float*)d_in[2];
    const float* w1    = (const float*)d_in[3];
    const float* b1    = (const float*)d_in[4];
    const float* w_out = (const float*)d_in[5];
    const float* b_out = (const float*)d_in[6];

    const int B = in_sizes[0] / 32;
    const int rows_per_block = (BLOCK / 32) * 64;  // 256
    const int grid = (B + rows_per_block - 1) / rows_per_block;

    armint_kernel<<<grid, BLOCK>>>(x, w0, b0, w1, b1, w_out, b_out,
                                   (float*)d_out, B);
}

// round 2
// speedup vs baseline: 1.1436x; 1.1436x over previous
#include <cuda_runtime.h>
#include <cstdint>

#define BLOCK 128
typedef unsigned long long ull;

// ---- packed f32x2 helpers (sm_103a) ----
__device__ __forceinline__ ull fma2(ull a, ull b, ull c) {
    ull d;
    asm("fma.rn.f32x2 %0, %1, %2, %3;" : "=l"(d) : "l"(a), "l"(b), "l"(c));
    return d;
}
__device__ __forceinline__ ull add2(ull a, ull b) {
    ull d;
    asm("add.rn.f32x2 %0, %1, %2;" : "=l"(d) : "l"(a), "l"(b));
    return d;
}
__device__ __forceinline__ ull pack2(float lo, float hi) {
    ull r;
    asm("mov.b64 %0, {%1, %2};" : "=l"(r) : "f"(lo), "f"(hi));
    return r;
}
__device__ __forceinline__ void unpack2(ull v, float& lo, float& hi) {
    asm("mov.b64 {%0, %1}, %2;" : "=f"(lo), "=f"(hi) : "l"(v));
}
__device__ __forceinline__ ull dup2(float v) {
    unsigned u = __float_as_uint(v);
    return ((ull)u << 32) | (ull)u;
}

// s16x2 pack/unpack for hidden activations (exact small non-negative integers)
__device__ __forceinline__ unsigned packs16(float a, float b) {  // low=a, high=b
    int ia = __float2int_rz(a), ib = __float2int_rz(b);
    unsigned r;
    asm("cvt.pack.sat.s16.s32 %0, %1, %2;" : "=r"(r) : "r"(ib), "r"(ia));
    return r;
}
__device__ __forceinline__ void unpacks16(unsigned p, float& a, float& b) {
    asm("{ .reg .b16 l, h;\n\t"
        "mov.b32 {l, h}, %2;\n\t"
        "cvt.rn.f32.s16 %0, l;\n\t"
        "cvt.rn.f32.s16 %1, h; }"
        : "=f"(a), "=f"(b) : "r"(p));
}

// relu + quantize fused: relu(trunc(xx/256 + copysign(.5,xx))) == trunc(max(xx,0)/256 + .5)
__device__ __forceinline__ float qrelu(float v) {
    return truncf(fmaf(fmaxf(v, 0.f), 0.00390625f, 0.5f));
}
// final-layer quantize (signed, no relu)
__device__ __forceinline__ float qfin(float v) {
    return truncf(fmaf(v, 0.00390625f, copysignf(0.5f, v)));
}

#define C256X2 0x4380000043800000ULL  // (256.f, 256.f)

__global__ void __launch_bounds__(BLOCK, 2) armint_kernel(
    const float* __restrict__ x,
    const float* __restrict__ w0, const float* __restrict__ b0,
    const float* __restrict__ w1, const float* __restrict__ b1,
    const float* __restrict__ w_out, const float* __restrict__ b_out,
    float* __restrict__ out, int B)
{
    // weights duplicated into both f32x2 halves, once per block
    __shared__ __align__(16) ull sw0[1024];
    __shared__ __align__(16) ull sw1[1024];
    __shared__ __align__(16) ull swo[64];
    __shared__ ull sb0[32], sb1[32], sbo[2];

    for (int i = threadIdx.x; i < 1024; i += BLOCK) {
        sw0[i] = dup2(w0[i]);
        sw1[i] = dup2(w1[i]);
    }
    if (threadIdx.x < 64) swo[threadIdx.x] = dup2(w_out[threadIdx.x]);
    if (threadIdx.x < 32) {
        sb0[threadIdx.x] = dup2(b0[threadIdx.x]);
        sb1[threadIdx.x] = dup2(b1[threadIdx.x]);
    }
    if (threadIdx.x < 2) sbo[threadIdx.x] = dup2(b_out[threadIdx.x]);
    __syncthreads();

    const int warp = threadIdx.x >> 5;
    const int lane = threadIdx.x & 31;
    // each warp owns 128 consecutive rows: two f32x2 pairs per thread
    const long long base = ((long long)blockIdx.x * (BLOCK / 32) + warp) * 128;
    const long long r0 = base + lane;        // pair0 lo
    const long long r1 = base + 32 + lane;   // pair0 hi
    const long long r2 = base + 64 + lane;   // pair1 lo
    const long long r3 = base + 96 + lane;   // pair1 hi
    const bool v0 = r0 < (long long)B;
    const bool v1 = r1 < (long long)B;
    const bool v2 = r2 < (long long)B;
    const bool v3 = r3 < (long long)B;

    // h = x * 256, two rows packed per f32x2 register, two pairs per thread
    ull h0[32], h1[32];
    {
        const float4* pa = (const float4*)(x + r0 * 32);
        const float4* pb = (const float4*)(x + r1 * 32);
        const float4* pc = (const float4*)(x + r2 * 32);
        const float4* pd = (const float4*)(x + r3 * 32);
        const float4 z = make_float4(0.f, 0.f, 0.f, 0.f);
        #pragma unroll
        for (int i = 0; i < 8; i++) {
            float4 a = v0 ? __ldcs(pa + i) : z;
            float4 b = v1 ? __ldcs(pb + i) : z;
            float4 c = v2 ? __ldcs(pc + i) : z;
            float4 d = v3 ? __ldcs(pd + i) : z;
            h0[4 * i + 0] = pack2(a.x * 256.f, b.x * 256.f);
            h0[4 * i + 1] = pack2(a.y * 256.f, b.y * 256.f);
            h0[4 * i + 2] = pack2(a.z * 256.f, b.z * 256.f);
            h0[4 * i + 3] = pack2(a.w * 256.f, b.w * 256.f);
            h1[4 * i + 0] = pack2(c.x * 256.f, d.x * 256.f);
            h1[4 * i + 1] = pack2(c.y * 256.f, d.y * 256.f);
            h1[4 * i + 2] = pack2(c.z * 256.f, d.z * 256.f);
            h1[4 * i + 3] = pack2(c.w * 256.f, d.w * 256.f);
        }
    }

    // hidden layer: xx = h@W^T + b + 256*h ; h' = relu(trunc((xx+sign*128)/256))
    // every weight load is shared by both row-pairs (4 rows).
    // new activations packed s16x2 to keep register count under 256.
    #define ARM_LAYER(SW, SB)                                                    \
    do {                                                                         \
        uint2 npk[32];                                                           \
        _Pragma("unroll")                                                        \
        for (int j = 0; j < 32; j++) {                                           \
            const ulonglong2* wr = (const ulonglong2*)((SW) + j * 32);           \
            ull a00 = fma2(h0[j], C256X2, (SB)[j]);                              \
            ull a01 = 0ULL;                                                      \
            ull a10 = fma2(h1[j], C256X2, (SB)[j]);                              \
            ull a11 = 0ULL;                                                      \
            _Pragma("unroll")                                                    \
            for (int kk = 0; kk < 16; kk++) {                                    \
                ulonglong2 w = wr[kk];                                           \
                a00 = fma2(h0[2 * kk + 0], w.x, a00);                            \
                a01 = fma2(h0[2 * kk + 1], w.y, a01);                            \
                a10 = fma2(h1[2 * kk + 0], w.x, a10);                            \
                a11 = fma2(h1[2 * kk + 1], w.y, a11);                            \
            }                                                                    \
            float q0, q1, q2, q3;                                                \
            unpack2(add2(a00, a01), q0, q1);                                     \
            unpack2(add2(a10, a11), q2, q3);                                     \
            npk[j].x = packs16(qrelu(q0), qrelu(q1));                            \
            npk[j].y = packs16(qrelu(q2), qrelu(q3));                            \
        }                                                                        \
        _Pragma("unroll")                                                        \
        for (int j = 0; j < 32; j++) {                                           \
            float a, b;                                                          \
            unpacks16(npk[j].x, a, b); h0[j] = pack2(a, b);                      \
            unpacks16(npk[j].y, a, b); h1[j] = pack2(a, b);                      \
        }                                                                        \
    } while (0)

    ARM_LAYER(sw0, sb0);
    ARM_LAYER(sw1, sb1);

    // output layer (2 neurons, no residual), raw = q/256
    float raw0[4], raw1[4];  // raw0 = mu per row, raw1 = log_scale per row
    #pragma unroll
    for (int j = 0; j < 2; j++) {
        const ulonglong2* wr = (const ulonglong2*)(swo + j * 32);
        ull a00 = sbo[j], a01 = 0ULL;
        ull a10 = sbo[j], a11 = 0ULL;
        #pragma unroll
        for (int kk = 0; kk < 16; kk++) {
            ulonglong2 w = wr[kk];
            a00 = fma2(h0[2 * kk + 0], w.x, a00);
            a01 = fma2(h0[2 * kk + 1], w.y, a01);
            a10 = fma2(h1[2 * kk + 0], w.x, a10);
            a11 = fma2(h1[2 * kk + 1], w.y, a11);
        }
        float q0, q1, q2, q3;
        unpack2(add2(a00, a01), q0, q1);
        unpack2(add2(a10, a11), q2, q3);
        float* dst = j == 0 ? raw0 : raw1;
        dst[0] = qfin(q0) * 0.00390625f;
        dst[1] = qfin(q1) * 0.00390625f;
        dst[2] = qfin(q2) * 0.00390625f;
        dst[3] = qfin(q3) * 0.00390625f;
    }

    const size_t Bz = (size_t)B;
    const long long rr[4] = {r0, r1, r2, r3};
    const bool vv[4] = {v0, v1, v2, v3};
    #pragma unroll
    for (int p = 0; p < 4; p++) {
        if (vv[p]) {
            float mu = raw0[p];
            float ls = raw1[p];
            float sc = expf(fminf(fmaxf(ls - 4.0f, -4.6f), 5.0f));
            out[(size_t)rr[p]]          = mu;
            out[Bz + (size_t)rr[p]]     = sc;
            out[2 * Bz + (size_t)rr[p]] = ls;
        }
    }
}

extern "C" void kernel_launch(void* const* d_in, const int* in_sizes, int n_in,
                              void* d_out, int out_size)
{
    const float* x     = (const float*)d_in[0];
    const float* w0    = (const float*)d_in[1];
    const float* b0    = (const float*)d_in[2];
    const float* w1    = (const float*)d_in[3];
    const float* b1    = (const float*)d_in[4];
    const float* w_out = (const float*)d_in[5];
    const float* b_out = (const float*)d_in[6];

    const int B = in_sizes[0] / 32;
    const int rows_per_block = (BLOCK / 32) * 128;  // 512
    const int grid = (B + rows_per_block - 1) / rows_per_block;

    armint_kernel<<<grid, BLOCK>>>(x, w0, b0, w1, b1, w_out, b_out,
                                   (float*)d_out, B);
}

// round 3
// speedup vs baseline: 3.5576x; 3.1109x over previous
#include <cuda_runtime.h>
#include <cuda_fp16.h>
#include <cstdint>

#define BLOCK 128

// m16n8k16 row.col f16*f16+f32
__device__ __forceinline__ void mma16816(float& c0, float& c1, float& c2, float& c3,
                                         unsigned a0, unsigned a1, unsigned a2, unsigned a3,
                                         unsigned b0, unsigned b1) {
    asm("mma.sync.aligned.m16n8k16.row.col.f32.f16.f16.f32 "
        "{%0,%1,%2,%3}, {%4,%5,%6,%7}, {%8,%9}, {%0,%1,%2,%3};"
        : "+f"(c0), "+f"(c1), "+f"(c2), "+f"(c3)
        : "r"(a0), "r"(a1), "r"(a2), "r"(a3), "r"(b0), "r"(b1));
}

__device__ __forceinline__ unsigned h2u(__half2 h) {
    return *reinterpret_cast<unsigned*>(&h);
}
__device__ __forceinline__ unsigned packh2(float lo, float hi) {
    __half2 h = __float22half2_rn(make_float2(lo, hi));
    return h2u(h);
}

// relu(trunc((xx+sign*128)/256)) == trunc(max(xx,0)/256 + 0.5)
__device__ __forceinline__ float qrelu(float v) {
    return truncf(fmaf(fmaxf(v, 0.f), 0.00390625f, 0.5f));
}
// signed quantize, no relu
__device__ __forceinline__ float qfin(float v) {
    return truncf(fmaf(v, 0.00390625f, copysignf(0.5f, v)));
}

__global__ void __launch_bounds__(BLOCK, 3) armint_kernel(
    const float* __restrict__ x,
    const float* __restrict__ w0, const float* __restrict__ b0,
    const float* __restrict__ w1, const float* __restrict__ b1,
    const float* __restrict__ w_out, const float* __restrict__ b_out,
    float* __restrict__ out, long long B)
{
    // f16 weights with residual folded into the diagonal (exact: integers <= ~320)
    __shared__ __half sw0[1024];
    __shared__ __half sw1[1024];
    __shared__ __half swo[64];
    __shared__ float sb0[32], sb1[32], sbo[2];

    for (int i = threadIdx.x; i < 1024; i += BLOCK) {
        int n = i >> 5, k = i & 31;
        float d = (n == k) ? 256.f : 0.f;
        sw0[i] = __float2half_rn(w0[i] + d);
        sw1[i] = __float2half_rn(w1[i] + d);
    }
    if (threadIdx.x < 64) swo[threadIdx.x] = __float2half_rn(w_out[threadIdx.x]);
    if (threadIdx.x < 32) { sb0[threadIdx.x] = b0[threadIdx.x]; sb1[threadIdx.x] = b1[threadIdx.x]; }
    if (threadIdx.x < 2)  sbo[threadIdx.x] = b_out[threadIdx.x];
    __syncthreads();

    const int warp = threadIdx.x >> 5;
    const int lane = threadIdx.x & 31;
    const int g = lane >> 2;   // 0..7
    const int t = lane & 3;    // 0..3

    // ---- per-thread weight fragments (persistent, no LDS in main loop) ----
    // B frag (k16 x n8, col): b0 = {W(n, k0), W(n, k0+1)}, b1 = {W(n, k0+8), W(n, k0+9)}
    // with n = 8*nt + g, k0 = 16*kt + 2*t. Adjacent k -> one 32-bit LDS.
    unsigned WB0[2][4][2], WB1[2][4][2], WB2[2][2];
    #pragma unroll
    for (int kt = 0; kt < 2; kt++)
        #pragma unroll
        for (int nt = 0; nt < 4; nt++) {
            int n = 8 * nt + g, k0 = 16 * kt + 2 * t;
            WB0[kt][nt][0] = *(const unsigned*)&sw0[n * 32 + k0];
            WB0[kt][nt][1] = *(const unsigned*)&sw0[n * 32 + k0 + 8];
            WB1[kt][nt][0] = *(const unsigned*)&sw1[n * 32 + k0];
            WB1[kt][nt][1] = *(const unsigned*)&sw1[n * 32 + k0 + 8];
        }
    #pragma unroll
    for (int kt = 0; kt < 2; kt++) {
        int k0 = 16 * kt + 2 * t;
        if (g < 2) {
            WB2[kt][0] = *(const unsigned*)&swo[g * 32 + k0];
            WB2[kt][1] = *(const unsigned*)&swo[g * 32 + k0 + 8];
        } else {
            WB2[kt][0] = 0u; WB2[kt][1] = 0u;
        }
    }
    // biases per owned C column (cols 8*nt + 2t, +1)
    float be0[4], bo0[4], be1[4], bo1[4];
    #pragma unroll
    for (int nt = 0; nt < 4; nt++) {
        be0[nt] = sb0[8 * nt + 2 * t]; bo0[nt] = sb0[8 * nt + 2 * t + 1];
        be1[nt] = sb1[8 * nt + 2 * t]; bo1[nt] = sb1[8 * nt + 2 * t + 1];
    }
    const float beo = (t == 0) ? sbo[0] : 0.f;
    const float boo = (t == 0) ? sbo[1] : 0.f;

    // ---- rows for this warp ----
    const long long rb = (long long)blockIdx.x * 128 + (long long)warp * 32;

    // ---- load x, build hi/lo f16 A fragments of x*256 ----
    unsigned AH[2][2][4], AL[2][2][4];   // [mtile][ktile][reg]
    #pragma unroll
    for (int mt = 0; mt < 2; mt++)
        #pragma unroll
        for (int kt = 0; kt < 2; kt++)
            #pragma unroll
            for (int r = 0; r < 4; r++) {
                long long row = rb + 16 * mt + g + ((r & 1) ? 8 : 0);
                int col = 16 * kt + 2 * t + ((r & 2) ? 8 : 0);
                if (row >= B) row = B - 1;  // safe clamp (B divisible by 128 in practice)
                float2 v = *(const float2*)(x + row * 32 + col);
                v.x *= 256.f; v.y *= 256.f;
                __half2 hh = __float22half2_rn(v);
                float2 hb = __half22float2(hh);
                __half2 ll = __float22half2_rn(make_float2(v.x - hb.x, v.y - hb.y));
                AH[mt][kt][r] = h2u(hh);
                AL[mt][kt][r] = h2u(ll);
            }

    // ---- layer 1: C = (hi+lo) @ W0'^T ----
    float C[2][4][4];
    #pragma unroll
    for (int mt = 0; mt < 2; mt++)
        #pragma unroll
        for (int nt = 0; nt < 4; nt++) {
            #pragma unroll
            for (int c = 0; c < 4; c++) C[mt][nt][c] = 0.f;
            #pragma unroll
            for (int kt = 0; kt < 2; kt++) {
                mma16816(C[mt][nt][0], C[mt][nt][1], C[mt][nt][2], C[mt][nt][3],
                         AH[mt][kt][0], AH[mt][kt][1], AH[mt][kt][2], AH[mt][kt][3],
                         WB0[kt][nt][0], WB0[kt][nt][1]);
                mma16816(C[mt][nt][0], C[mt][nt][1], C[mt][nt][2], C[mt][nt][3],
                         AL[mt][kt][0], AL[mt][kt][1], AL[mt][kt][2], AL[mt][kt][3],
                         WB0[kt][nt][0], WB0[kt][nt][1]);
            }
        }

    // ---- quantize -> A fragments for layer 2 (C(m16n16) layout == A(m16k16) layout) ----
    unsigned A[2][2][4];
    #pragma unroll
    for (int mt = 0; mt < 2; mt++)
        #pragma unroll
        for (int kn = 0; kn < 2; kn++) {     // next ktile kn <- ntiles 2kn, 2kn+1
            int n0 = 2 * kn, n1 = 2 * kn + 1;
            A[mt][kn][0] = packh2(qrelu(C[mt][n0][0] + be0[n0]), qrelu(C[mt][n0][1] + bo0[n0]));
            A[mt][kn][1] = packh2(qrelu(C[mt][n0][2] + be0[n0]), qrelu(C[mt][n0][3] + bo0[n0]));
            A[mt][kn][2] = packh2(qrelu(C[mt][n1][0] + be0[n1]), qrelu(C[mt][n1][1] + bo0[n1]));
            A[mt][kn][3] = packh2(qrelu(C[mt][n1][2] + be0[n1]), qrelu(C[mt][n1][3] + bo0[n1]));
        }

    // ---- layer 2 ----
    #pragma unroll
    for (int mt = 0; mt < 2; mt++)
        #pragma unroll
        for (int nt = 0; nt < 4; nt++) {
            #pragma unroll
            for (int c = 0; c < 4; c++) C[mt][nt][c] = 0.f;
            #pragma unroll
            for (int kt = 0; kt < 2; kt++)
                mma16816(C[mt][nt][0], C[mt][nt][1], C[mt][nt][2], C[mt][nt][3],
                         A[mt][kt][0], A[mt][kt][1], A[mt][kt][2], A[mt][kt][3],
                         WB1[kt][nt][0], WB1[kt][nt][1]);
        }

    #pragma unroll
    for (int mt = 0; mt < 2; mt++)
        #pragma unroll
        for (int kn = 0; kn < 2; kn++) {
            int n0 = 2 * kn, n1 = 2 * kn + 1;
            A[mt][kn][0] = packh2(qrelu(C[mt][n0][0] + be1[n0]), qrelu(C[mt][n0][1] + bo1[n0]));
            A[mt][kn][1] = packh2(qrelu(C[mt][n0][2] + be1[n0]), qrelu(C[mt][n0][3] + bo1[n0]));
            A[mt][kn][2] = packh2(qrelu(C[mt][n1][0] + be1[n1]), qrelu(C[mt][n1][1] + bo1[n1]));
            A[mt][kn][3] = packh2(qrelu(C[mt][n1][2] + be1[n1]), qrelu(C[mt][n1][3] + bo1[n1]));
        }

    // ---- layer 3: 2 output neurons in ntile 0 ----
    float D[2][4];
    #pragma unroll
    for (int mt = 0; mt < 2; mt++) {
        #pragma unroll
        for (int c = 0; c < 4; c++) D[mt][c] = 0.f;
        #pragma unroll
        for (int kt = 0; kt < 2; kt++)
            mma16816(D[mt][0], D[mt][1], D[mt][2], D[mt][3],
                     A[mt][kt][0], A[mt][kt][1], A[mt][kt][2], A[mt][kt][3],
                     WB2[kt][0], WB2[kt][1]);
    }

    // ---- epilogue: only t==0 lanes hold cols 0 (mu) and 1 (log_scale) ----
    if (t == 0) {
        #pragma unroll
        for (int mt = 0; mt < 2; mt++) {
            #pragma unroll
            for (int half = 0; half < 2; half++) {
                long long row = rb + 16 * mt + g + (half ? 8 : 0);
                float vmu = D[mt][half ? 2 : 0] + beo;
                float vls = D[mt][half ? 3 : 1] + boo;
                float mu = qfin(vmu) * 0.00390625f;
                float ls = qfin(vls) * 0.00390625f;
                float sc = expf(fminf(fmaxf(ls - 4.0f, -4.6f), 5.0f));
                if (row < B) {
                    out[row]         = mu;
                    out[B + row]     = sc;
                    out[2 * B + row] = ls;
                }
            }
        }
    }
}

extern "C" void kernel_launch(void* const* d_in, const int* in_sizes, int n_in,
                              void* d_out, int out_size)
{
    const float* x     = (const float*)d_in[0];
    const float* w0    = (const float*)d_in[1];
    const float* b0    = (const float*)d_in[2];
    const float* w1    = (const float*)d_in[3];
    const float* b1    = (const float*)d_in[4];
    const float* w_out = (const float*)d_in[5];
    const float* b_out = (const float*)d_in[6];

    const long long B = in_sizes[0] / 32;
    const int grid = (int)((B + 127) / 128);

    armint_kernel<<<grid, BLOCK>>>(x, w0, b0, w1, b1, w_out, b_out,
                                   (float*)d_out, B);
}

// round 4
// speedup vs baseline: 3.8175x; 1.0731x over previous
#include <cuda_runtime.h>
#include <cuda_fp16.h>
#include <cstdint>

#define BLOCK 128
typedef unsigned long long ull;

// m16n8k16 row.col f16*f16+f32
__device__ __forceinline__ void mma16816(float& c0, float& c1, float& c2, float& c3,
                                         unsigned a0, unsigned a1, unsigned a2, unsigned a3,
                                         unsigned b0, unsigned b1) {
    asm("mma.sync.aligned.m16n8k16.row.col.f32.f16.f16.f32 "
        "{%0,%1,%2,%3}, {%4,%5,%6,%7}, {%8,%9}, {%0,%1,%2,%3};"
        : "+f"(c0), "+f"(c1), "+f"(c2), "+f"(c3)
        : "r"(a0), "r"(a1), "r"(a2), "r"(a3), "r"(b0), "r"(b1));
}

__device__ __forceinline__ ull mul2(ull a, ull b) {
    ull d; asm("mul.rn.f32x2 %0, %1, %2;" : "=l"(d) : "l"(a), "l"(b)); return d;
}
__device__ __forceinline__ ull sub2(ull a, ull b) {
    ull d; asm("sub.rn.f32x2 %0, %1, %2;" : "=l"(d) : "l"(a), "l"(b)); return d;
}
__device__ __forceinline__ ull pack2(float lo, float hi) {
    ull r; asm("mov.b64 %0, {%1, %2};" : "=l"(r) : "f"(lo), "f"(hi)); return r;
}
__device__ __forceinline__ void unpack2(ull v, float& lo, float& hi) {
    asm("mov.b64 {%0, %1}, %2;" : "=f"(lo), "=f"(hi) : "l"(v));
}
__device__ __forceinline__ unsigned h2u(__half2 h) { return *reinterpret_cast<unsigned*>(&h); }
__device__ __forceinline__ unsigned packh2(float lo, float hi) {
    return h2u(__float22half2_rn(make_float2(lo, hi)));
}

// relu + quantize: relu(trunc((v+sign*128)/256)) == trunc(max(v,0)/256 + 0.5)
__device__ __forceinline__ float qrelu(float v) {
    return truncf(fmaf(fmaxf(v, 0.f), 0.00390625f, 0.5f));
}
// signed quantize, no relu
__device__ __forceinline__ float qfin(float v) {
    return truncf(fmaf(v, 0.00390625f, copysignf(0.5f, v)));
}

#define C256X2 0x4380000043800000ULL  // (256.f, 256.f)

__global__ void __launch_bounds__(BLOCK, 3) armint_kernel(
    const float* __restrict__ x,
    const float* __restrict__ w0, const float* __restrict__ b0,
    const float* __restrict__ w1, const float* __restrict__ b1,
    const float* __restrict__ w_out, const float* __restrict__ b_out,
    float* __restrict__ out, long long B)
{
    // f16 weights, residual (256*I) folded into the diagonal (all exact integers)
    // sw0 is stored COLUMN-PERMUTED: MMA k-position p within each 16-wide ktile
    // maps to actual feature sigma(p) = 4t + 2b + e  (p = 2t + e + 8b).
    // This lets x be loaded as contiguous float4 per lane.
    __shared__ __half sw0[1024];
    __shared__ __half sw1[1024];
    __shared__ __half swo[64];
    __shared__ float sb0[32], sb1[32], sbo[2];

    for (int i = threadIdx.x; i < 1024; i += BLOCK) {
        int n = i >> 5, kidx = i & 31;
        int kt = kidx >> 4, p = kidx & 15;
        int tt = (p >> 1) & 3, e = p & 1, bb = (p >> 3) & 1;
        int src = kt * 16 + 4 * tt + 2 * bb + e;       // sigma
        sw0[i] = __float2half_rn(w0[n * 32 + src] + (n == src ? 256.f : 0.f));
        sw1[i] = __float2half_rn(w1[i] + (n == kidx ? 256.f : 0.f));
    }
    if (threadIdx.x < 64) swo[threadIdx.x] = __float2half_rn(w_out[threadIdx.x]);
    if (threadIdx.x < 32) { sb0[threadIdx.x] = b0[threadIdx.x]; sb1[threadIdx.x] = b1[threadIdx.x]; }
    if (threadIdx.x < 2)  sbo[threadIdx.x] = b_out[threadIdx.x];
    __syncthreads();

    const int warp = threadIdx.x >> 5;
    const int lane = threadIdx.x & 31;
    const int g = lane >> 2;   // 0..7
    const int t = lane & 3;    // 0..3

    // ---- persistent per-thread weight fragments ----
    unsigned WB0[2][4][2], WB1[2][4][2], WB2[2][2];
    #pragma unroll
    for (int kt = 0; kt < 2; kt++)
        #pragma unroll
        for (int nt = 0; nt < 4; nt++) {
            int n = 8 * nt + g, k0 = 16 * kt + 2 * t;
            WB0[kt][nt][0] = *(const unsigned*)&sw0[n * 32 + k0];
            WB0[kt][nt][1] = *(const unsigned*)&sw0[n * 32 + k0 + 8];
            WB1[kt][nt][0] = *(const unsigned*)&sw1[n * 32 + k0];
            WB1[kt][nt][1] = *(const unsigned*)&sw1[n * 32 + k0 + 8];
        }
    #pragma unroll
    for (int kt = 0; kt < 2; kt++) {
        int k0 = 16 * kt + 2 * t;
        if (g < 2) {
            WB2[kt][0] = *(const unsigned*)&swo[g * 32 + k0];
            WB2[kt][1] = *(const unsigned*)&swo[g * 32 + k0 + 8];
        } else { WB2[kt][0] = 0u; WB2[kt][1] = 0u; }
    }
    // biases for owned C columns (cols 8*nt + 2t, +1)
    float be0[4], bo0[4], be1[4], bo1[4];
    #pragma unroll
    for (int nt = 0; nt < 4; nt++) {
        be0[nt] = sb0[8 * nt + 2 * t]; bo0[nt] = sb0[8 * nt + 2 * t + 1];
        be1[nt] = sb1[8 * nt + 2 * t]; bo1[nt] = sb1[8 * nt + 2 * t + 1];
    }
    const float beo = sbo[0];   // only meaningful on t==0 lanes (cols 0,1)
    const float boo = sbo[1];

    const long long rb = (long long)blockIdx.x * 128 + (long long)warp * 32;

    // ---- load x as contiguous float4 per lane; hi/lo f16 split of x*256 ----
    // lane (g,t), tile (mt,kt), row-half rh: row = rb+16mt+g+8rh, cols 16kt+4t..+3
    // float4 components map to A-positions (2t, 2t+1, 2t+8, 2t+9) via sigma.
    unsigned AH[2][2][4], AL[2][2][4];
    #pragma unroll
    for (int mt = 0; mt < 2; mt++)
        #pragma unroll
        for (int rh = 0; rh < 2; rh++) {
            long long row = rb + 16 * mt + g + 8 * rh;
            if (row >= B) row = B - 1;
            #pragma unroll
            for (int kt = 0; kt < 2; kt++) {
                float4 v = __ldcs((const float4*)(x + row * 32 + kt * 16 + 4 * t));
                ull p01 = mul2(pack2(v.x, v.y), C256X2);
                ull p23 = mul2(pack2(v.z, v.w), C256X2);
                float a, b;
                unpack2(p01, a, b);
                __half2 h01 = __float22half2_rn(make_float2(a, b));
                float2 hb01 = __half22float2(h01);
                ull l01 = sub2(p01, pack2(hb01.x, hb01.y));
                unpack2(p23, a, b);
                __half2 h23 = __float22half2_rn(make_float2(a, b));
                float2 hb23 = __half22float2(h23);
                ull l23 = sub2(p23, pack2(hb23.x, hb23.y));
                float la, lb;
                AH[mt][kt][rh]     = h2u(h01);
                AH[mt][kt][2 + rh] = h2u(h23);
                unpack2(l01, la, lb); AL[mt][kt][rh]     = packh2(la, lb);
                unpack2(l23, la, lb); AL[mt][kt][2 + rh] = packh2(la, lb);
            }
        }

    // ---- layer 1: C = bias + (hi+lo) @ W0'^T  (bias folded into accumulator init)
    float C[2][4][4];
    #pragma unroll
    for (int mt = 0; mt < 2; mt++)
        #pragma unroll
        for (int nt = 0; nt < 4; nt++) {
            C[mt][nt][0] = be0[nt]; C[mt][nt][1] = bo0[nt];
            C[mt][nt][2] = be0[nt]; C[mt][nt][3] = bo0[nt];
            #pragma unroll
            for (int kt = 0; kt < 2; kt++) {
                mma16816(C[mt][nt][0], C[mt][nt][1], C[mt][nt][2], C[mt][nt][3],
                         AH[mt][kt][0], AH[mt][kt][1], AH[mt][kt][2], AH[mt][kt][3],
                         WB0[kt][nt][0], WB0[kt][nt][1]);
                mma16816(C[mt][nt][0], C[mt][nt][1], C[mt][nt][2], C[mt][nt][3],
                         AL[mt][kt][0], AL[mt][kt][1], AL[mt][kt][2], AL[mt][kt][3],
                         WB0[kt][nt][0], WB0[kt][nt][1]);
            }
        }

    // ---- quantize -> A fragments for layer 2 (C(m16n16) layout == A(m16k16) layout)
    unsigned A[2][2][4];
    #pragma unroll
    for (int mt = 0; mt < 2; mt++)
        #pragma unroll
        for (int kn = 0; kn < 2; kn++) {
            int n0 = 2 * kn, n1 = 2 * kn + 1;
            A[mt][kn][0] = packh2(qrelu(C[mt][n0][0]), qrelu(C[mt][n0][1]));
            A[mt][kn][1] = packh2(qrelu(C[mt][n0][2]), qrelu(C[mt][n0][3]));
            A[mt][kn][2] = packh2(qrelu(C[mt][n1][0]), qrelu(C[mt][n1][1]));
            A[mt][kn][3] = packh2(qrelu(C[mt][n1][2]), qrelu(C[mt][n1][3]));
        }

    // ---- layer 2 ----
    #pragma unroll
    for (int mt = 0; mt < 2; mt++)
        #pragma unroll
        for (int nt = 0; nt < 4; nt++) {
            C[mt][nt][0] = be1[nt]; C[mt][nt][1] = bo1[nt];
            C[mt][nt][2] = be1[nt]; C[mt][nt][3] = bo1[nt];
            #pragma unroll
            for (int kt = 0; kt < 2; kt++)
                mma16816(C[mt][nt][0], C[mt][nt][1], C[mt][nt][2], C[mt][nt][3],
                         A[mt][kt][0], A[mt][kt][1], A[mt][kt][2], A[mt][kt][3],
                         WB1[kt][nt][0], WB1[kt][nt][1]);
        }

    #pragma unroll
    for (int mt = 0; mt < 2; mt++)
        #pragma unroll
        for (int kn = 0; kn < 2; kn++) {
            int n0 = 2 * kn, n1 = 2 * kn + 1;
            A[mt][kn][0] = packh2(qrelu(C[mt][n0][0]), qrelu(C[mt][n0][1]));
            A[mt][kn][1] = packh2(qrelu(C[mt][n0][2]), qrelu(C[mt][n0][3]));
            A[mt][kn][2] = packh2(qrelu(C[mt][n1][0]), qrelu(C[mt][n1][1]));
            A[mt][kn][3] = packh2(qrelu(C[mt][n1][2]), qrelu(C[mt][n1][3]));
        }

    // ---- layer 3: 2 output neurons live in ntile 0, cols 0/1 (t==0 lanes)
    float D[2][4];
    #pragma unroll
    for (int mt = 0; mt < 2; mt++) {
        D[mt][0] = beo; D[mt][1] = boo; D[mt][2] = beo; D[mt][3] = boo;
        #pragma unroll
        for (int kt = 0; kt < 2; kt++)
            mma16816(D[mt][0], D[mt][1], D[mt][2], D[mt][3],
                     A[mt][kt][0], A[mt][kt][1], A[mt][kt][2], A[mt][kt][3],
                     WB2[kt][0], WB2[kt][1]);
    }

    // ---- epilogue ----
    if (t == 0) {
        #pragma unroll
        for (int mt = 0; mt < 2; mt++)
            #pragma unroll
            for (int half = 0; half < 2; half++) {
                long long row = rb + 16 * mt + g + (half ? 8 : 0);
                float mu = qfin(D[mt][half ? 2 : 0]) * 0.00390625f;
                float ls = qfin(D[mt][half ? 3 : 1]) * 0.00390625f;
                float sc = expf(fminf(fmaxf(ls - 4.0f, -4.6f), 5.0f));
                if (row < B) {
                    out[row]         = mu;
                    out[B + row]     = sc;
                    out[2 * B + row] = ls;
                }
            }
    }
}

extern "C" void kernel_launch(void* const* d_in, const int* in_sizes, int n_in,
                              void* d_out, int out_size)
{
    const float* x     = (const float*)d_in[0];
    const float* w0    = (const float*)d_in[1];
    const float* b0    = (const float*)d_in[2];
    const float* w1    = (const float*)d_in[3];
    const float* b1    = (const float*)d_in[4];
    const float* w_out = (const float*)d_in[5];
    const float* b_out = (const float*)d_in[6];

    const long long B = in_sizes[0] / 32;
    const int grid = (int)((B + 127) / 128);

    armint_kernel<<<grid, BLOCK>>>(x, w0, b0, w1, b1, w_out, b_out,
                                   (float*)d_out, B);
}